// round 3
// baseline (speedup 1.0000x reference)
#include <cuda_runtime.h>

#define EPS 1e-12f

__device__ __forceinline__ float micro_scale(
    float lx, float ly, float lz,
    float nx, float ny, float nz,
    float vx, float vy, float vz,
    float e)
{
    // half vector
    float hx = lx + vx, hy = ly + vy, hz = lz + vz;
    float hnorm = sqrtf(hx * hx + hy * hy + hz * hz);
    float inv = 1.0f / fmaxf(hnorm, EPS);
    hx *= inv; hy *= inv; hz *= inv;

    float nl = nx * lx + ny * ly + nz * lz;
    float nv = nx * vx + ny * vy + nz * vz;
    float vh = vx * hx + vy * hy + vz * hz;

    float d_term = 0.0f;
    float g_term = nl * nv;

    float c  = vh;
    float gg = e * e + c * c - 1.0f;
    float gs = sqrtf(fmaxf(gg, EPS));
    float a  = (gs - c) / (gs + c);
    float b  = (c * (gs + c) - 1.0f) / (c * (gs - c) + 1.0f);
    float fr = (gg > 0.0f) ? (0.5f * a * a * (1.0f + b * b)) : 1.0f;

    float denom = 4.0f * nl * nv;
    return d_term * g_term * fr / denom;
}

// 4 points per thread: 36 floats in = 9 float4 loads, 12 floats out = 3 float4 stores.
__global__ void microfacet_kernel4(const float4* __restrict__ in4,
                                   const float* __restrict__ base_color,
                                   const float* __restrict__ eta_p,
                                   float4* __restrict__ out4,
                                   int ngroups)   // number of 4-point groups (full)
{
    int g = blockIdx.x * blockDim.x + threadIdx.x;
    if (g >= ngroups) return;

    float e   = __ldg(eta_p);
    float bc0 = __ldg(base_color + 0);
    float bc1 = __ldg(base_color + 1);
    float bc2 = __ldg(base_color + 2);

    const float4* p4 = in4 + (size_t)g * 9;
    float4 q[9];
    #pragma unroll
    for (int j = 0; j < 9; j++) q[j] = p4[j];

    const float* f = (const float*)q;   // 36 floats = 4 points x 9

    float s[4];
    #pragma unroll
    for (int k = 0; k < 4; k++) {
        const float* p = f + k * 9;
        s[k] = micro_scale(p[0], p[1], p[2],
                           p[3], p[4], p[5],
                           p[6], p[7], p[8], e);
    }

    // 12 output floats: [s0*bc, s1*bc, s2*bc, s3*bc]
    float o[12];
    #pragma unroll
    for (int k = 0; k < 4; k++) {
        o[k * 3 + 0] = bc0 * s[k];
        o[k * 3 + 1] = bc1 * s[k];
        o[k * 3 + 2] = bc2 * s[k];
    }

    float4* dst = out4 + (size_t)g * 3;
    const float4* ov = (const float4*)o;
    #pragma unroll
    for (int j = 0; j < 3; j++) dst[j] = ov[j];
}

// Scalar tail for points not covered by full groups of 4.
__global__ void microfacet_tail(const float* __restrict__ in,
                                const float* __restrict__ base_color,
                                const float* __restrict__ eta_p,
                                float* __restrict__ out,
                                int start, int n)
{
    int i = start + blockIdx.x * blockDim.x + threadIdx.x;
    if (i >= n) return;

    float e   = __ldg(eta_p);
    float bc0 = __ldg(base_color + 0);
    float bc1 = __ldg(base_color + 1);
    float bc2 = __ldg(base_color + 2);

    const float* p = in + (size_t)i * 9;
    float s = micro_scale(p[0], p[1], p[2],
                          p[3], p[4], p[5],
                          p[6], p[7], p[8], e);
    float* o = out + (size_t)i * 3;
    o[0] = bc0 * s;
    o[1] = bc1 * s;
    o[2] = bc2 * s;
}

extern "C" void kernel_launch(void* const* d_in, const int* in_sizes, int n_in,
                              void* d_out, int out_size)
{
    const float* in         = (const float*)d_in[0];
    const float* base_color = (const float*)d_in[1];
    // d_in[2] is alpha (unused by the reference math)
    const float* eta        = (const float*)d_in[3];
    float* out = (float*)d_out;

    int n = in_sizes[0] / 9;
    int ngroups = n / 4;

    if (ngroups > 0) {
        int threads = 256;
        int blocks = (ngroups + threads - 1) / threads;
        microfacet_kernel4<<<blocks, threads>>>(
            (const float4*)in, base_color, eta, (float4*)out, ngroups);
    }
    int tail = n - ngroups * 4;
    if (tail > 0) {
        microfacet_tail<<<1, 128>>>(in, base_color, eta, out, ngroups * 4, n);
    }
}